// round 10
// baseline (speedup 1.0000x reference)
#include <cuda_runtime.h>

// Problem constants (fixed by dataset)
#define T_IN  60
#define CH    128
#define NPIX  4096
#define HID   128
#define G4    512            // 4*HID
#define RBLK  32             // rows per CTA
#define NCTA  (NPIX / RBLK)  // 128
#define NTH   512            // threads per CTA (16 warps)
#define KT    32             // K tile
#define PH    34             // hT pitch (odd 8B-bank stride -> conflict-free STS.64)

typedef unsigned long long ull;

// Prepared weights (device globals, ~770KB; allowed)
__device__ __align__(16) float g_WtCat[256 * G4];  // [k][g]: k<128 -> W_hh, k>=128 -> W_ih
__device__ __align__(16) float g_WsumT[128 * G4];  // [k][g]: W_ih + W_hh (AR phase)
__device__ __align__(16) float g_bias[G4];

__global__ void prep_kernel(const float* __restrict__ W_ih, const float* __restrict__ W_hh,
                            const float* __restrict__ b_ih, const float* __restrict__ b_hh) {
    int idx = blockIdx.x * blockDim.x + threadIdx.x;
    if (idx < 128 * G4) {
        int k = idx >> 9;
        int g = idx & 511;
        float wih = W_ih[g * CH + k];
        float whh = W_hh[g * HID + k];
        g_WtCat[k * G4 + g]         = whh;
        g_WtCat[(128 + k) * G4 + g] = wih;
        g_WsumT[k * G4 + g]         = wih + whh;
    }
    if (idx < G4) g_bias[idx] = b_ih[idx] + b_hh[idx];
}

__device__ __forceinline__ float sigm(float x) {
    return __fdividef(1.0f, 1.0f + __expf(-x));
}
__device__ __forceinline__ float tanh_f(float x) {
    return 2.0f * __fdividef(1.0f, 1.0f + __expf(-2.0f * x)) - 1.0f;
}

// packed f32x2 helpers
__device__ __forceinline__ ull dup2(float v) {
    ull r; asm("mov.b64 %0, {%1, %1};" : "=l"(r) : "f"(v)); return r;
}
#define FFMA2(acc, a, b) asm("fma.rn.f32x2 %0, %1, %2, %0;" : "+l"(acc) : "l"(a), "l"(b))
#define UNPACK2(lo, hi, v) asm("mov.b64 {%0, %1}, %2;" : "=f"(lo), "=f"(hi) : "l"(v))

// cp.async helpers
#define CP_ASYNC16(dst_u32, src_ptr) \
    asm volatile("cp.async.cg.shared.global [%0], [%1], 16;" :: "r"(dst_u32), "l"(src_ptr))
#define CP_COMMIT()    asm volatile("cp.async.commit_group;")
#define CP_WAIT_G2()   asm volatile("cp.async.wait_group 2;")

// Dynamic smem layout (floats):
//   [0,     4352)  hT   [128][34]  h transposed: hT[k][r] (row pairs)
//   [4352,  8448)  shx  [128][32]  x transposed
//   [8448, 24832)  buf0 [32][512]  weight K-tile (TRIPLE buffered)
//   [24832,41216)  buf1
//   [41216,57600)  buf2
#define OFF_X  4352
#define OFF_B0 8448
#define OFF_B1 24832
#define OFF_B2 41216
#define SMEM_FLOATS 57600
#define SMEM_BYTES  (SMEM_FLOATS * 4)   // 230400 B <= 232448 cap

extern __shared__ float smem[];

__device__ __forceinline__ void prefetchB(const float* __restrict__ src, float* dst, int tid) {
    unsigned dsh = (unsigned)__cvta_generic_to_shared(dst);
    #pragma unroll
    for (int i = 0; i < 8; ++i) {
        int off = (tid + NTH * i) * 4;        // floats (16B chunks)
        CP_ASYNC16(dsh + off * 4, src + off);
    }
}

__device__ __forceinline__ void prefetchX(const float* __restrict__ image, float* sh_x,
                                          int t, int row_base, int tid) {
    unsigned dsh = (unsigned)__cvta_generic_to_shared(sh_x);
    #pragma unroll
    for (int q = 0; q < 2; ++q) {
        int idx  = tid + NTH * q;             // 0..1023
        int c    = idx >> 3;                  // channel
        int part = idx & 7;                   // 16B chunk of the 32-row stripe
        const float* src = image + ((size_t)t * CH + c) * (size_t)NPIX + row_base + part * 4;
        CP_ASYNC16(dsh + (c * RBLK + part * 4) * 4, src);
    }
}

// advance (t, i) by one tile in the global tile sequence
__device__ __forceinline__ void adv_tile(int& tt, int& ii) {
    int nt = (tt < T_IN) ? 8 : 4;
    if (++ii == nt) { ii = 0; ++tt; }
}

__global__ __launch_bounds__(NTH, 1)
void lstm_persist_kernel(const float* __restrict__ image, float* __restrict__ out, int total_t) {
    float* hT  = smem;
    float* shx = smem + OFF_X;
    float* bufs[3] = { smem + OFF_B0, smem + OFF_B1, smem + OFF_B2 };

    const int tid = threadIdx.x;
    const int tx  = tid & 31;
    const int w   = tid >> 5;     // warp 0..15
    const int rg  = w >> 2;       // row group: rows rg*8 .. rg*8+7
    const int cq  = w & 3;        // column quarter
    const int jc  = tx + 32 * cq; // column within each gate block (0..127)
    const int row_base = blockIdx.x * RBLK;

    for (int i = tid; i < 128 * PH; i += NTH) hT[i] = 0.0f;

    // bias in registers (constant over steps); cell state in registers.
    ull bias_r[4];
    #pragma unroll
    for (int g = 0; g < 4; ++g) bias_r[g] = dup2(g_bias[jc + 128 * g]);
    float c_lo[4] = {0.f, 0.f, 0.f, 0.f};
    float c_hi[4] = {0.f, 0.f, 0.f, 0.f};

    // prologue: tiles 0 and 1 pre-staged (two committed groups), x(0) rides in group 0
    prefetchB(g_WtCat, bufs[0], tid);
    prefetchX(image, shx, 0, row_base, tid);
    CP_COMMIT();
    prefetchB(g_WtCat + (size_t)KT * G4, bufs[1], tid);
    CP_COMMIT();
    __syncthreads();   // orders hT init

    int bcur = 0;      // buffer index of the tile about to be computed

    for (int t = 0; t < total_t; ++t) {
        const bool ph1 = (t < T_IN);
        const int  nt  = ph1 ? 8 : 4;

        // accumulators: 4 row-pairs x 4 gate blocks, bias-fused
        ull acc[4][4];
        #pragma unroll
        for (int g = 0; g < 4; ++g) {
            #pragma unroll
            for (int q = 0; q < 4; ++q) acc[q][g] = bias_r[g];
        }

        for (int i = 0; i < nt; ++i) {
            // all warps done with previous tile -> safe to overwrite buf[(bcur+2)%3]
            __syncthreads();

            // two-ahead prefetch (always commit, even empty, to keep group invariant)
            {
                int t2 = t, i2 = i;
                adv_tile(t2, i2); adv_tile(t2, i2);
                if (t2 < total_t) {
                    const float* nB = ((t2 < T_IN) ? g_WtCat : g_WsumT) + (size_t)(i2 * KT) * G4;
                    int bnext = bcur + 2; if (bnext >= 3) bnext -= 3;
                    prefetchB(nB, bufs[bnext], tid);
                }
                if (ph1 && i == 0 && t > 0)   // x(t): all x(t-1) reads finished at this barrier
                    prefetchX(image, shx, t, row_base, tid);
                CP_COMMIT();
            }

            // group for THIS tile was committed two tiles ago -> wait is a no-op
            CP_WAIT_G2();

            const float* bc = bufs[bcur];
            const int kt = i * KT;

            if (kt < 128) {
                // A from transposed hidden state hT[k][r] (row-pair LDS.64 broadcast)
                const float* ab = hT + kt * PH + rg * 8;
                #pragma unroll 4
                for (int kk = 0; kk < KT; ++kk) {
                    const float* br = bc + kk * G4 + jc;
                    ull a0 = *(const ull*)(ab + kk * PH + 0);
                    ull a1 = *(const ull*)(ab + kk * PH + 2);
                    ull a2 = *(const ull*)(ab + kk * PH + 4);
                    ull a3 = *(const ull*)(ab + kk * PH + 6);
                    ull b0 = dup2(br[0]);
                    ull b1 = dup2(br[128]);
                    ull b2 = dup2(br[256]);
                    ull b3 = dup2(br[384]);
                    FFMA2(acc[0][0], a0, b0); FFMA2(acc[0][1], a0, b1);
                    FFMA2(acc[0][2], a0, b2); FFMA2(acc[0][3], a0, b3);
                    FFMA2(acc[1][0], a1, b0); FFMA2(acc[1][1], a1, b1);
                    FFMA2(acc[1][2], a1, b2); FFMA2(acc[1][3], a1, b3);
                    FFMA2(acc[2][0], a2, b0); FFMA2(acc[2][1], a2, b1);
                    FFMA2(acc[2][2], a2, b2); FFMA2(acc[2][3], a2, b3);
                    FFMA2(acc[3][0], a3, b0); FFMA2(acc[3][1], a3, b1);
                    FFMA2(acc[3][2], a3, b2); FFMA2(acc[3][3], a3, b3);
                }
            } else {
                // A from transposed input tile shx[c][r]
                const float* ab = shx + (kt - 128) * RBLK + rg * 8;
                #pragma unroll 4
                for (int kk = 0; kk < KT; ++kk) {
                    const float* br = bc + kk * G4 + jc;
                    ull a0 = *(const ull*)(ab + kk * RBLK + 0);
                    ull a1 = *(const ull*)(ab + kk * RBLK + 2);
                    ull a2 = *(const ull*)(ab + kk * RBLK + 4);
                    ull a3 = *(const ull*)(ab + kk * RBLK + 6);
                    ull b0 = dup2(br[0]);
                    ull b1 = dup2(br[128]);
                    ull b2 = dup2(br[256]);
                    ull b3 = dup2(br[384]);
                    FFMA2(acc[0][0], a0, b0); FFMA2(acc[0][1], a0, b1);
                    FFMA2(acc[0][2], a0, b2); FFMA2(acc[0][3], a0, b3);
                    FFMA2(acc[1][0], a1, b0); FFMA2(acc[1][1], a1, b1);
                    FFMA2(acc[1][2], a1, b2); FFMA2(acc[1][3], a1, b3);
                    FFMA2(acc[2][0], a2, b0); FFMA2(acc[2][1], a2, b1);
                    FFMA2(acc[2][2], a2, b2); FFMA2(acc[2][3], a2, b3);
                    FFMA2(acc[3][0], a3, b0); FFMA2(acc[3][1], a3, b1);
                    FFMA2(acc[3][2], a3, b2); FFMA2(acc[3][3], a3, b3);
                }
            }
            ++bcur; if (bcur == 3) bcur = 0;
        }

        // AR phase: all tiles read hT -> drain before epilogue overwrites it.
        // Phase1: last 4 tiles read shx/bufs only, epilogue may proceed unsynced.
        if (!ph1) __syncthreads();

        // epilogue: fully register-resident LSTM cell update (c lives in registers)
        #pragma unroll
        for (int q = 0; q < 4; ++q) {
            float i0, i1, f0, f1, g0, g1, o0, o1;
            UNPACK2(i0, i1, acc[q][0]);
            UNPACK2(f0, f1, acc[q][1]);
            UNPACK2(g0, g1, acc[q][2]);
            UNPACK2(o0, o1, acc[q][3]);
            int r0 = rg * 8 + 2 * q;
            float cn0 = sigm(f0) * c_lo[q] + sigm(i0) * tanh_f(g0);
            float cn1 = sigm(f1) * c_hi[q] + sigm(i1) * tanh_f(g1);
            c_lo[q] = cn0;
            c_hi[q] = cn1;
            float hn0 = sigm(o0) * tanh_f(cn0);
            float hn1 = sigm(o1) * tanh_f(cn1);
            *(float2*)(hT + jc * PH + r0) = make_float2(hn0, hn1);
            out[((size_t)(row_base + r0)     * total_t + t) * HID + jc] = hn0;
            out[((size_t)(row_base + r0 + 1) * total_t + t) * HID + jc] = hn1;
        }
        // next step's tile-0 top __syncthreads orders hT writes vs GEMM reads
    }
}

extern "C" void kernel_launch(void* const* d_in, const int* in_sizes, int n_in,
                              void* d_out, int out_size) {
    const float* image = (const float*)d_in[0];
    // d_in[1] = mask (unused by reference forward)
    const float* W_ih  = (const float*)d_in[2];
    const float* W_hh  = (const float*)d_in[3];
    const float* b_ih  = (const float*)d_in[4];
    const float* b_hh  = (const float*)d_in[5];
    float* out = (float*)d_out;

    int total_t = out_size / (NPIX * HID);   // 114

    prep_kernel<<<(128 * G4 + 255) / 256, 256>>>(W_ih, W_hh, b_ih, b_hh);

    cudaFuncSetAttribute(lstm_persist_kernel,
                         cudaFuncAttributeMaxDynamicSharedMemorySize, SMEM_BYTES);
    lstm_persist_kernel<<<NCTA, NTH, SMEM_BYTES>>>(image, out, total_t);
}